// round 16
// baseline (speedup 1.0000x reference)
#include <cuda_runtime.h>
#include <math.h>

#define BB 2
#define TT 8192
#define HQ 32
#define HH 8
#define DD 64
#define DRR 16
#define NB 128
#define BS 64
#define SELK 16
#define GRP 4
#define TOK_TILE 128
#define TPAD 132   // padded row stride of transposed Kr (conflict-free)

typedef unsigned long long u64;

__device__ float g_Kr[BB * NB * HH * DRR];

// ---------------- Kernel 1: block-mean of K, then project with Wk (unchanged) ----------------
__global__ void kr_kernel(const float* __restrict__ K, const float* __restrict__ Wk) {
    int n = blockIdx.x, h = blockIdx.y, b = blockIdx.z;
    int d = threadIdx.x;  // 64 threads, one per dim
    __shared__ float sm[DD];

    const float* kp = K + ((size_t)((b * TT + n * BS) * HH + h)) * DD + d;
    float acc = 0.f;
#pragma unroll 4
    for (int j = 0; j < BS; ++j) acc += kp[(size_t)j * HH * DD];
    sm[d] = acc * (1.0f / BS);
    __syncthreads();

    if (d < DRR) {
        int r = d;
        const float* wk = Wk + (h * DD) * DRR + r;
        float a = 0.f;
#pragma unroll
        for (int dd = 0; dd < DD; ++dd) a = fmaf(sm[dd], wk[dd * DRR], a);
        g_Kr[((b * NB + n) * HH + h) * DRR + r] = a;
    }
}

// ---------------- f32x2 helpers (each lane rounds exactly like the scalar op) ----------------
__device__ __forceinline__ u64 ffma2(u64 a, u64 b, u64 c) {
    u64 d;
    asm("fma.rn.f32x2 %0, %1, %2, %3;" : "=l"(d) : "l"(a), "l"(b), "l"(c));
    return d;
}
__device__ __forceinline__ u64 fmul2(u64 a, u64 b) {
    u64 d;
    asm("mul.rn.f32x2 %0, %1, %2;" : "=l"(d) : "l"(a), "l"(b));
    return d;
}
__device__ __forceinline__ u64 pack2(float x, float y) {
    u64 r;
    asm("mov.b64 %0, {%1, %2};" : "=l"(r) : "f"(x), "f"(y));
    return r;
}
__device__ __forceinline__ void unpack2(u64 v, float& x, float& y) {
    asm("mov.b64 {%0, %1}, %2;" : "=f"(x), "=f"(y) : "l"(v));
}

// ---------------- sorting-network helpers (values only) ----------------
__device__ __forceinline__ void ce_asc(float& a, float& b) {
    float mn = fminf(a, b), mx = fmaxf(a, b);
    a = mn; b = mx;
}
__device__ __forceinline__ void sort16_asc(float (&v)[16]) {
#pragma unroll
    for (int k = 2; k <= 16; k <<= 1) {
#pragma unroll
        for (int j = k >> 1; j > 0; j >>= 1) {
#pragma unroll
            for (int i = 0; i < 16; ++i) {
                int l = i ^ j;
                if (l > i) {
                    if ((i & k) == 0) ce_asc(v[i], v[l]);
                    else              ce_asc(v[l], v[i]);
                }
            }
        }
    }
}
__device__ __forceinline__ void bitonic_clean16_asc(float (&v)[16]) {
#pragma unroll
    for (int j = 8; j > 0; j >>= 1) {
#pragma unroll
        for (int i = 0; i < 16; ++i) {
            if ((i & j) == 0) ce_asc(v[i], v[i | j]);
        }
    }
}

// ---------------- Kernel 2: 2 threads/token, balanced chunks, f32x2 scoring ----------------
__global__ __launch_bounds__(TOK_TILE, 7) void router_kernel(
    const float* __restrict__ Q, const float* __restrict__ Wq,
    const float* __restrict__ ls, float* __restrict__ out) {
    int k = blockIdx.x;          // 0..127
    int h = blockIdx.y, b = blockIdx.z;
    int tid = threadIdx.x, warp = tid >> 5, lane = tid & 31;
    int j16 = lane & 15, role = lane >> 4;   // 16 tokens/warp, 2 roles/token

    __shared__ __align__(16) float sWq[DD * DRR];    // 4 KB  [d][r]
    __shared__ __align__(16) float sKrT[DRR * TPAD]; // 8.25 KB transposed [r][n]

    for (int i = tid; i < DD * DRR; i += TOK_TILE) sWq[i] = Wq[h * DD * DRR + i];
    for (int i = tid; i < NB * DRR; i += TOK_TILE) {
        int n = i >> 4, r = i & 15;
        sKrT[r * TPAD + n] = g_Kr[((b * NB + n) * HH + h) * DRR + r];
    }
    __syncthreads();

    // balanced 16-token chunks: CTA k -> {k, 128+k, 383-k, 511-k}; sum(tb)=254 const.
    int c = (warp == 0) ? k : (warp == 1) ? (128 + k) : (warp == 2) ? (383 - k) : (511 - k);
    int t = c * 16 + j16;
    int tb = c >> 2;            // == t>>6, warp-uniform
    float scale = expf(ls[h]);

    // ---- Qr: each role computes its 8-r half with identical serial-d chains ----
    const float4* qrow = (const float4*)(Q + ((size_t)((b * TT + t) * HQ + h * GRP)) * DD);
    u64 QR2h[4];
#pragma unroll
    for (int i = 0; i < 4; ++i) QR2h[i] = 0ull;
    int kk0 = role * 2;   // ulonglong2 index: pairs r2 = {2kk0..2kk0+3} = role's r-half
#pragma unroll 4
    for (int d4 = 0; d4 < DD / 4; ++d4) {
        float4 q4 = qrow[d4];
        float qv[4] = {q4.x, q4.y, q4.z, q4.w};
#pragma unroll
        for (int sub = 0; sub < 4; ++sub) {
            u64 qq = pack2(qv[sub], qv[sub]);
            const ulonglong2* wrow = (const ulonglong2*)&sWq[(d4 * 4 + sub) * DRR];
            ulonglong2 wA = wrow[kk0], wB = wrow[kk0 + 1];
            QR2h[0] = ffma2(qq, wA.x, QR2h[0]);
            QR2h[1] = ffma2(qq, wA.y, QR2h[1]);
            QR2h[2] = ffma2(qq, wB.x, QR2h[2]);
            QR2h[3] = ffma2(qq, wB.y, QR2h[3]);
        }
    }
    // exchange halves with partner (bits unchanged)
    u64 oth[4];
#pragma unroll
    for (int i = 0; i < 4; ++i) oth[i] = __shfl_xor_sync(0xffffffffu, QR2h[i], 16);
    float Qr[DRR];
    if (role == 0) {
#pragma unroll
        for (int i = 0; i < 4; ++i) { unpack2(QR2h[i], Qr[2*i], Qr[2*i+1]); unpack2(oth[i], Qr[8+2*i], Qr[8+2*i+1]); }
    } else {
#pragma unroll
        for (int i = 0; i < 4; ++i) { unpack2(QR2h[i], Qr[8+2*i], Qr[8+2*i+1]); unpack2(oth[i], Qr[2*i], Qr[2*i+1]); }
    }
    u64 qr2[DRR];
#pragma unroll
    for (int r = 0; r < DRR; ++r) qr2[r] = pack2(Qr[r], Qr[r]);
    u64 scale2 = pack2(scale, scale);

    const float NEG_INF = __int_as_float(0xff800000);

    // ---- pass 1: tau; roles take interleaved 16-score batches ----
    float s[16];
#pragma unroll
    for (int j = 0; j < 16; ++j) s[j] = NEG_INF;  // ascending (s[0] = 16th largest)

    int nbatch = (tb >> 4) + 1;
    int nloop = (nbatch + 1) >> 1;   // warp-uniform
#pragma unroll 1
    for (int it = 0; it < nloop; ++it) {
        int base = (2 * it + role) * 16;   // role-interleaved; may exceed tb (masked)
        u64 acc2[8];
#pragma unroll
        for (int j = 0; j < 8; ++j) acc2[j] = 0ull;
#pragma unroll
        for (int r = 0; r < DRR; ++r) {
            const ulonglong2* p = (const ulonglong2*)&sKrT[r * TPAD + base];
            ulonglong2 p0 = p[0], p1 = p[1], p2 = p[2], p3 = p[3];
            u64 q = qr2[r];
            acc2[0] = ffma2(q, p0.x, acc2[0]); acc2[1] = ffma2(q, p0.y, acc2[1]);
            acc2[2] = ffma2(q, p1.x, acc2[2]); acc2[3] = ffma2(q, p1.y, acc2[3]);
            acc2[4] = ffma2(q, p2.x, acc2[4]); acc2[5] = ffma2(q, p2.y, acc2[5]);
            acc2[6] = ffma2(q, p3.x, acc2[6]); acc2[7] = ffma2(q, p3.y, acc2[7]);
        }
        float Bv[16];
#pragma unroll
        for (int j = 0; j < 8; ++j) {
            u64 m = fmul2(acc2[j], scale2);
            unpack2(m, Bv[2 * j], Bv[2 * j + 1]);
        }
        if (it == nloop - 1) {           // tail (lim may be negative -> all masked)
            int lim = tb - base;
#pragma unroll
            for (int i = 0; i < 16; ++i) Bv[i] = (i <= lim) ? Bv[i] : NEG_INF;
        }
        sort16_asc(Bv);
#pragma unroll
        for (int i = 0; i < 16; ++i) s[i] = fmaxf(s[i], Bv[15 - i]);
        bitonic_clean16_asc(s);
    }
    // merge with partner's top-16 (union top-16; identical result on both roles)
    float ps[16];
#pragma unroll
    for (int i = 0; i < 16; ++i) ps[i] = __shfl_xor_sync(0xffffffffu, s[i], 16);
#pragma unroll
    for (int i = 0; i < 16; ++i) s[i] = fmaxf(s[i], ps[15 - i]);
    bitonic_clean16_asc(s);
    float tau = (tb >= 15) ? s[0] : -1e30f;

    // ---- pass 2: masks; roles take interleaved groups of 4 (never straddle n=64) ----
    u64 gt_lo = 0, eq_lo = 0, gt_hi = 0, eq_hi = 0;
    int G = (tb >> 2) + 1;
    int gloop = (G + 1) >> 1;        // warp-uniform
#pragma unroll 2
    for (int it = 0; it < gloop; ++it) {
        int n = 4 * (2 * it + role);   // may exceed tb (guarded); reads stay < 128
        u64 accA = 0ull, accB = 0ull;
#pragma unroll
        for (int r = 0; r < DRR; ++r) {
            ulonglong2 w = *(const ulonglong2*)&sKrT[r * TPAD + n];
            u64 q = qr2[r];
            accA = ffma2(q, w.x, accA);
            accB = ffma2(q, w.y, accB);
        }
        accA = fmul2(accA, scale2); accB = fmul2(accB, scale2);
        float sc[4];
        unpack2(accA, sc[0], sc[1]); unpack2(accB, sc[2], sc[3]);
        if (n < 64) {
#pragma unroll
            for (int j = 0; j < 4; ++j) {
                if (n + j <= tb) {
                    u64 bit = 1ull << (n + j);
                    if (sc[j] > tau) gt_lo |= bit;
                    else if (sc[j] == tau) eq_lo |= bit;
                }
            }
        } else {
#pragma unroll
            for (int j = 0; j < 4; ++j) {
                if (n + j <= tb) {
                    u64 bit = 1ull << (n + j - 64);
                    if (sc[j] > tau) gt_hi |= bit;
                    else if (sc[j] == tau) eq_hi |= bit;
                }
            }
        }
    }
    // combine role-disjoint masks
    gt_lo |= __shfl_xor_sync(0xffffffffu, gt_lo, 16);
    eq_lo |= __shfl_xor_sync(0xffffffffu, eq_lo, 16);
    gt_hi |= __shfl_xor_sync(0xffffffffu, gt_hi, 16);
    eq_hi |= __shfl_xor_sync(0xffffffffu, eq_hi, 16);

    if (tb < 15) {
        gt_lo |= ((1ull << 15) - (2ull << tb));  // surrogate masked blocks tb+1..14 (> tau)
        eq_lo |= (1ull << 15);                   // surrogate block 15 (tie)
    }

    // tie-fill: lowest-index ==tau bits until 16 selected (jax stable tie rule)
    int need = 16 - __popcll(gt_lo) - __popcll(gt_hi);
    u64 sel_lo = gt_lo, sel_hi = gt_hi;
#pragma unroll 1
    for (int it = 0; it < 16 && need > 0; ++it) {
        if (eq_lo) { u64 bb = eq_lo & (0ull - eq_lo); sel_lo |= bb; eq_lo ^= bb; }
        else if (eq_hi) { u64 bb = eq_hi & (0ull - eq_hi); sel_hi |= bb; eq_hi ^= bb; }
        --need;
    }

    // ---- emit: merge ascending bit-walk with 2 local blocks, keep 16 smallest ----
    int l0 = tb;
    int l1 = tb > 0 ? tb - 1 : 0;  // l1 <= l0
    int li = 0;
    int r[16];
#pragma unroll
    for (int kk = 0; kk < 16; ++kk) {
        bool lo_nz = (sel_lo != 0ull);
        int nb = lo_nz ? (__ffsll((long long)sel_lo) - 1)
                       : (64 + __ffsll((long long)sel_hi) - 1);
        int lc = (li == 0) ? l1 : ((li == 1) ? l0 : 0x7FFFFFFF);
        bool tl = (lc <= nb);
        r[kk] = tl ? lc : nb;
        li += tl ? 1 : 0;
        if (!tl) {
            if (lo_nz) sel_lo &= (sel_lo - 1ull);
            else       sel_hi &= (sel_hi - 1ull);
        }
    }

    // output dtype float32; roles split the 4x float4 stores
    float* op = out + ((size_t)((b * TT + t) * HH + h)) * SELK;
    float4* op4 = (float4*)op;
    if (role == 0) {
        op4[0] = make_float4((float)r[0],  (float)r[1],  (float)r[2],  (float)r[3]);
        op4[1] = make_float4((float)r[4],  (float)r[5],  (float)r[6],  (float)r[7]);
    } else {
        op4[2] = make_float4((float)r[8],  (float)r[9],  (float)r[10], (float)r[11]);
        op4[3] = make_float4((float)r[12], (float)r[13], (float)r[14], (float)r[15]);
    }
}

// ---------------- launch: identify inputs by element count (unchanged, passing) ----------------
extern "C" void kernel_launch(void* const* d_in, const int* in_sizes, int n_in,
                              void* d_out, int out_size) {
    const long long SZ_Q  = (long long)BB * TT * HQ * DD;  // 33554432
    const long long SZ_K  = (long long)BB * TT * HH * DD;  // 8388608
    const long long SZ_W  = HH * DD * DRR;                 // 8192
    const long long SZ_LS = HH;                            // 8

    long long unit = 1;
    for (int i = 0; i < n_in; ++i)
        if ((long long)in_sizes[i] == SZ_Q * 4) unit = 4;

    int iQ = -1, iK = -1, iW1 = -1, iW2 = -1, iLS = -1;
    for (int i = 0; i < n_in; ++i) {
        long long s = (long long)in_sizes[i];
        if (s == SZ_Q * unit) iQ = i;
        else if (s == SZ_K * unit) iK = i;
        else if (s == SZ_W * unit) { if (iW1 < 0) iW1 = i; else iW2 = i; }
        else if (s == SZ_LS * unit) iLS = i;
    }
    int iWq = (iQ >= 0 && iK >= 0 && iQ < iK) ? iW1 : iW2;
    int iWk = (iQ >= 0 && iK >= 0 && iQ < iK) ? iW2 : iW1;
    if (iQ < 0) iQ = 0;
    if (iK < 0) iK = 1;
    if (iWq < 0) iWq = 2;
    if (iWk < 0) iWk = 3;
    if (iLS < 0) iLS = 4;

    const float* Q  = (const float*)d_in[iQ];
    const float* K  = (const float*)d_in[iK];
    const float* Wq = (const float*)d_in[iWq];
    const float* Wk = (const float*)d_in[iWk];
    const float* ls = (const float*)d_in[iLS];
    float* out = (float*)d_out;

    dim3 g1(NB, HH, BB);
    kr_kernel<<<g1, 64>>>(K, Wk);

    dim3 g2(128, HH, BB);   // 128 CTAs x 4 warps x 16 tokens: 128*64 = 8192 tokens per (b,h)
    router_kernel<<<g2, TOK_TILE>>>(Q, Wq, ls, out);
}

// round 17
// speedup vs baseline: 1.1470x; 1.1470x over previous
#include <cuda_runtime.h>
#include <math.h>

#define BB 2
#define TT 8192
#define HQ 32
#define HH 8
#define DD 64
#define DRR 16
#define NB 128
#define BS 64
#define SELK 16
#define GRP 4
#define TOK_TILE 128
#define TPAD 132   // padded row stride of transposed Kr (conflict-free)

typedef unsigned long long u64;

__device__ float g_Kr[BB * NB * HH * DRR];
// score cache: [chunk_global(4096)][n4(32)][lane(32)][4] = 64 MB, coalesced both ways
__device__ float g_S[16777216];

// ---------------- Kernel 1: block-mean of K, then project with Wk (unchanged) ----------------
__global__ void kr_kernel(const float* __restrict__ K, const float* __restrict__ Wk) {
    int n = blockIdx.x, h = blockIdx.y, b = blockIdx.z;
    int d = threadIdx.x;  // 64 threads, one per dim
    __shared__ float sm[DD];

    const float* kp = K + ((size_t)((b * TT + n * BS) * HH + h)) * DD + d;
    float acc = 0.f;
#pragma unroll 4
    for (int j = 0; j < BS; ++j) acc += kp[(size_t)j * HH * DD];
    sm[d] = acc * (1.0f / BS);
    __syncthreads();

    if (d < DRR) {
        int r = d;
        const float* wk = Wk + (h * DD) * DRR + r;
        float a = 0.f;
#pragma unroll
        for (int dd = 0; dd < DD; ++dd) a = fmaf(sm[dd], wk[dd * DRR], a);
        g_Kr[((b * NB + n) * HH + h) * DRR + r] = a;
    }
}

// ---------------- f32x2 helpers (each lane rounds exactly like the scalar op) ----------------
__device__ __forceinline__ u64 ffma2(u64 a, u64 b, u64 c) {
    u64 d;
    asm("fma.rn.f32x2 %0, %1, %2, %3;" : "=l"(d) : "l"(a), "l"(b), "l"(c));
    return d;
}
__device__ __forceinline__ u64 fmul2(u64 a, u64 b) {
    u64 d;
    asm("mul.rn.f32x2 %0, %1, %2;" : "=l"(d) : "l"(a), "l"(b));
    return d;
}
__device__ __forceinline__ u64 pack2(float x, float y) {
    u64 r;
    asm("mov.b64 %0, {%1, %2};" : "=l"(r) : "f"(x), "f"(y));
    return r;
}
__device__ __forceinline__ void unpack2(u64 v, float& x, float& y) {
    asm("mov.b64 {%0, %1}, %2;" : "=f"(x), "=f"(y) : "l"(v));
}

// ---------------- sorting-network helpers (values only) ----------------
__device__ __forceinline__ void ce_asc(float& a, float& b) {
    float mn = fminf(a, b), mx = fmaxf(a, b);
    a = mn; b = mx;
}
__device__ __forceinline__ void sort16_asc(float (&v)[16]) {
#pragma unroll
    for (int k = 2; k <= 16; k <<= 1) {
#pragma unroll
        for (int j = k >> 1; j > 0; j >>= 1) {
#pragma unroll
            for (int i = 0; i < 16; ++i) {
                int l = i ^ j;
                if (l > i) {
                    if ((i & k) == 0) ce_asc(v[i], v[l]);
                    else              ce_asc(v[l], v[i]);
                }
            }
        }
    }
}
__device__ __forceinline__ void bitonic_clean16_asc(float (&v)[16]) {
#pragma unroll
    for (int j = 8; j > 0; j >>= 1) {
#pragma unroll
        for (int i = 0; i < 16; ++i) {
            if ((i & j) == 0) ce_asc(v[i], v[i | j]);
        }
    }
}

// ---------------- Kernel 2: balanced chunks, f32x2 scoring, cached-score pass 2 ----------------
__global__ __launch_bounds__(TOK_TILE, 7) void router_kernel(
    const float* __restrict__ Q, const float* __restrict__ Wq,
    const float* __restrict__ ls, float* __restrict__ out) {
    int k = blockIdx.x;          // 0..63
    int h = blockIdx.y, b = blockIdx.z;
    int tid = threadIdx.x, warp = tid >> 5, lane = tid & 31;

    __shared__ __align__(16) float sWq[DD * DRR];    // 4 KB  [d][r]
    __shared__ __align__(16) float sKrT[DRR * TPAD]; // 8.25 KB transposed [r][n]

    for (int i = tid; i < DD * DRR; i += TOK_TILE) sWq[i] = Wq[h * DD * DRR + i];
    for (int i = tid; i < NB * DRR; i += TOK_TILE) {
        int n = i >> 4, r = i & 15;  // coalesced read, padded transpose write
        sKrT[r * TPAD + n] = g_Kr[((b * NB + n) * HH + h) * DRR + r];
    }
    __syncthreads();

    // balanced 32-token chunks: CTA k -> {k, 64+k, 191-k, 255-k}; sum(tb)=254 const.
    int c = (warp == 0) ? k : (warp == 1) ? (64 + k) : (warp == 2) ? (191 - k) : (255 - k);
    int t = c * 32 + lane;
    int tb = c >> 1;  // == t >> 6, warp-uniform
    float scale = expf(ls[h]);
    int chunk_global = (b * HH + h) * 256 + c;
    float* myS = g_S + (size_t)chunk_global * 4096 + lane * 4;  // stride 128 floats per n4

    // Qr = Q-row @ Wq[h] — f32x2-packed, bit-exact vs scalar (R14 verbatim)
    const float4* qrow = (const float4*)(Q + ((size_t)((b * TT + t) * HQ + h * GRP)) * DD);
    u64 QR2[8];
#pragma unroll
    for (int r2 = 0; r2 < 8; ++r2) QR2[r2] = 0ull;
#pragma unroll 4
    for (int d4 = 0; d4 < DD / 4; ++d4) {
        float4 q4 = qrow[d4];
        float qv[4] = {q4.x, q4.y, q4.z, q4.w};
#pragma unroll
        for (int sub = 0; sub < 4; ++sub) {
            u64 qq = pack2(qv[sub], qv[sub]);
            const ulonglong2* wrow = (const ulonglong2*)&sWq[(d4 * 4 + sub) * DRR];
#pragma unroll
            for (int kk = 0; kk < 4; ++kk) {
                ulonglong2 w2 = wrow[kk];
                QR2[2 * kk]     = ffma2(qq, w2.x, QR2[2 * kk]);
                QR2[2 * kk + 1] = ffma2(qq, w2.y, QR2[2 * kk + 1]);
            }
        }
    }
    u64 qr2[DRR];
#pragma unroll
    for (int r2 = 0; r2 < 8; ++r2) {
        float x, y;
        unpack2(QR2[r2], x, y);
        qr2[2 * r2]     = pack2(x, x);
        qr2[2 * r2 + 1] = pack2(y, y);
    }
    u64 scale2 = pack2(scale, scale);

    const float NEG_INF = __int_as_float(0xff800000);

    // ---- pass 1: tau; 16 scores as 8 packed chains per batch; CACHE raw scores ----
    float s[16];
#pragma unroll
    for (int j = 0; j < 16; ++j) s[j] = NEG_INF;  // ascending (s[0] = 16th largest)

    int nbatch = (tb >> 4) + 1;  // warp-uniform
#pragma unroll 1
    for (int bt = 0; bt < nbatch; ++bt) {
        int base = bt * 16;
        u64 acc2[8];
#pragma unroll
        for (int j = 0; j < 8; ++j) acc2[j] = 0ull;
#pragma unroll
        for (int r = 0; r < DRR; ++r) {
            const ulonglong2* p = (const ulonglong2*)&sKrT[r * TPAD + base];
            ulonglong2 p0 = p[0], p1 = p[1], p2 = p[2], p3 = p[3];
            u64 q = qr2[r];
            acc2[0] = ffma2(q, p0.x, acc2[0]); acc2[1] = ffma2(q, p0.y, acc2[1]);
            acc2[2] = ffma2(q, p1.x, acc2[2]); acc2[3] = ffma2(q, p1.y, acc2[3]);
            acc2[4] = ffma2(q, p2.x, acc2[4]); acc2[5] = ffma2(q, p2.y, acc2[5]);
            acc2[6] = ffma2(q, p3.x, acc2[6]); acc2[7] = ffma2(q, p3.y, acc2[7]);
        }
        float Bv[16];
#pragma unroll
        for (int j = 0; j < 8; ++j) {
            u64 m = fmul2(acc2[j], scale2);
            unpack2(m, Bv[2 * j], Bv[2 * j + 1]);
        }
        // cache RAW scores (pre-mask) — coalesced: warp writes 512B contiguous per store
        float4* dst = (float4*)(myS + (size_t)(bt * 4) * 128);
#pragma unroll
        for (int kk = 0; kk < 4; ++kk) {
            dst[(size_t)kk * 32] = make_float4(Bv[4 * kk], Bv[4 * kk + 1],
                                               Bv[4 * kk + 2], Bv[4 * kk + 3]);
        }
        if (bt == nbatch - 1) {          // warp-uniform tail mask
            int lim = tb - base;         // 0..15
#pragma unroll
            for (int i = 0; i < 16; ++i) Bv[i] = (i <= lim) ? Bv[i] : NEG_INF;
        }
        sort16_asc(Bv);
#pragma unroll
        for (int i = 0; i < 16; ++i) s[i] = fmaxf(s[i], Bv[15 - i]);
        bitonic_clean16_asc(s);
    }
    float tau = (tb >= 15) ? s[0] : -1e30f;

    // ---- pass 2: masks from CACHED scores (same bits; same-thread RAW ordering) ----
    u64 gt_lo = 0, eq_lo = 0, gt_hi = 0, eq_hi = 0;
    int G = tb + 1;
    int fullg = G >> 2;
    const float4* sp = (const float4*)myS;
#pragma unroll 4
    for (int g = 0; g < fullg; ++g) {
        float4 v = sp[(size_t)g * 32];
        int n = g * 4;
        float sc[4] = {v.x, v.y, v.z, v.w};
        if (n < 64) {   // groups of 4 never straddle n=64
#pragma unroll
            for (int j = 0; j < 4; ++j) {
                u64 bit = 1ull << (n + j);
                if (sc[j] > tau) gt_lo |= bit;
                else if (sc[j] == tau) eq_lo |= bit;
            }
        } else {
#pragma unroll
            for (int j = 0; j < 4; ++j) {
                u64 bit = 1ull << (n + j - 64);
                if (sc[j] > tau) gt_hi |= bit;
                else if (sc[j] == tau) eq_hi |= bit;
            }
        }
    }
    int rem = G & 3;
    if (rem) {
        float4 v = sp[(size_t)fullg * 32];
        int n = fullg * 4;
        float sc[4] = {v.x, v.y, v.z, v.w};
        if (n < 64) {
#pragma unroll
            for (int j = 0; j < 3; ++j) {
                if (j < rem) {
                    u64 bit = 1ull << (n + j);
                    if (sc[j] > tau) gt_lo |= bit;
                    else if (sc[j] == tau) eq_lo |= bit;
                }
            }
        } else {
#pragma unroll
            for (int j = 0; j < 3; ++j) {
                if (j < rem) {
                    u64 bit = 1ull << (n + j - 64);
                    if (sc[j] > tau) gt_hi |= bit;
                    else if (sc[j] == tau) eq_hi |= bit;
                }
            }
        }
    }
    if (tb < 15) {
        gt_lo |= ((1ull << 15) - (2ull << tb));  // surrogate masked blocks tb+1..14 (> tau)
        eq_lo |= (1ull << 15);                   // surrogate block 15 (tie)
    }

    // tie-fill: lowest-index ==tau bits until 16 selected (jax stable tie rule)
    int need = 16 - __popcll(gt_lo) - __popcll(gt_hi);
    u64 sel_lo = gt_lo, sel_hi = gt_hi;
#pragma unroll 1
    for (int it = 0; it < 16 && need > 0; ++it) {
        if (eq_lo) { u64 bb = eq_lo & (0ull - eq_lo); sel_lo |= bb; eq_lo ^= bb; }
        else if (eq_hi) { u64 bb = eq_hi & (0ull - eq_hi); sel_hi |= bb; eq_hi ^= bb; }
        --need;
    }

    // ---- emit: merge ascending bit-walk with 2 local blocks, keep 16 smallest ----
    int l0 = tb;
    int l1 = tb > 0 ? tb - 1 : 0;  // l1 <= l0
    int li = 0;
    int r[16];
#pragma unroll
    for (int kk = 0; kk < 16; ++kk) {
        bool lo_nz = (sel_lo != 0ull);
        int nb = lo_nz ? (__ffsll((long long)sel_lo) - 1)
                       : (64 + __ffsll((long long)sel_hi) - 1);
        int lc = (li == 0) ? l1 : ((li == 1) ? l0 : 0x7FFFFFFF);
        bool tl = (lc <= nb);
        r[kk] = tl ? lc : nb;
        li += tl ? 1 : 0;
        if (!tl) {
            if (lo_nz) sel_lo &= (sel_lo - 1ull);
            else       sel_hi &= (sel_hi - 1ull);
        }
    }

    // output dtype is float32 (R7 finding)
    float* op = out + ((size_t)((b * TT + t) * HH + h)) * SELK;
    float4* op4 = (float4*)op;
    op4[0] = make_float4((float)r[0],  (float)r[1],  (float)r[2],  (float)r[3]);
    op4[1] = make_float4((float)r[4],  (float)r[5],  (float)r[6],  (float)r[7]);
    op4[2] = make_float4((float)r[8],  (float)r[9],  (float)r[10], (float)r[11]);
    op4[3] = make_float4((float)r[12], (float)r[13], (float)r[14], (float)r[15]);
}

// ---------------- launch: identify inputs by element count (unchanged, passing) ----------------
extern "C" void kernel_launch(void* const* d_in, const int* in_sizes, int n_in,
                              void* d_out, int out_size) {
    const long long SZ_Q  = (long long)BB * TT * HQ * DD;  // 33554432
    const long long SZ_K  = (long long)BB * TT * HH * DD;  // 8388608
    const long long SZ_W  = HH * DD * DRR;                 // 8192
    const long long SZ_LS = HH;                            // 8

    long long unit = 1;
    for (int i = 0; i < n_in; ++i)
        if ((long long)in_sizes[i] == SZ_Q * 4) unit = 4;

    int iQ = -1, iK = -1, iW1 = -1, iW2 = -1, iLS = -1;
    for (int i = 0; i < n_in; ++i) {
        long long s = (long long)in_sizes[i];
        if (s == SZ_Q * unit) iQ = i;
        else if (s == SZ_K * unit) iK = i;
        else if (s == SZ_W * unit) { if (iW1 < 0) iW1 = i; else iW2 = i; }
        else if (s == SZ_LS * unit) iLS = i;
    }
    int iWq = (iQ >= 0 && iK >= 0 && iQ < iK) ? iW1 : iW2;
    int iWk = (iQ >= 0 && iK >= 0 && iQ < iK) ? iW2 : iW1;
    if (iQ < 0) iQ = 0;
    if (iK < 0) iK = 1;
    if (iWq < 0) iWq = 2;
    if (iWk < 0) iWk = 3;
    if (iLS < 0) iLS = 4;

    const float* Q  = (const float*)d_in[iQ];
    const float* K  = (const float*)d_in[iK];
    const float* Wq = (const float*)d_in[iWq];
    const float* Wk = (const float*)d_in[iWk];
    const float* ls = (const float*)d_in[iLS];
    float* out = (float*)d_out;

    dim3 g1(NB, HH, BB);
    kr_kernel<<<g1, 64>>>(K, Wk);

    dim3 g2(64, HH, BB);   // 64 CTAs x 4 warps x 32 tokens = 8192 tokens per (b,h)
    router_kernel<<<g2, TOK_TILE>>>(Q, Wq, ls, out);
}